// round 15
// baseline (speedup 1.0000x reference)
#include <cuda_runtime.h>
#include <cuda_bf16.h>
#include <cstdint>
#include <cstddef>

#define B_ 4
#define N_ 256
#define D_ 256
#define H_ 8
#define DK_ 32
#define DV_ 32
#define R_ 64
#define BN_ (B_*N_)
#define EPS_ 1e-6f

typedef unsigned long long u64;

// ---------------- device scratch ----------------
__device__ float g_ER[R_ * D_];
__device__ float g_EV[R_ * D_];
__device__ float g_EVt[H_ * R_ * 32];            // [h][r][d] transposed EV
__device__ float g_Xq[B_ * H_ * N_ * DK_];
__device__ float g_Xk[B_ * H_ * N_ * DK_];
__device__ float g_Xv[B_ * H_ * N_ * DV_];
__device__ float g_Pq[B_ * N_ * H_ * R_];        // [b,i,h*64+r]
__device__ float g_S0[B_ * H_ * N_ * N_];
__device__ float g_Z2[B_ * H_ * N_ * DV_];
__device__ float g_Zc[BN_ * D_];

// ---------------- f32x2 helpers ----------------
__device__ __forceinline__ void fma2(u64& d, u64 a, u64 b) {
    asm("fma.rn.f32x2 %0, %1, %2, %3;" : "=l"(d) : "l"(a), "l"(b), "l"(d));
}
__device__ __forceinline__ u64 pack2(float x, float y) {
    u64 r; asm("mov.b64 %0, {%1, %2};" : "=l"(r) : "f"(x), "f"(y)); return r;
}
__device__ __forceinline__ float2 unpack2(u64 v) {
    float2 r; asm("mov.b64 {%0, %1}, %2;" : "=f"(r.x), "=f"(r.y) : "l"(v)); return r;
}

// ---------------- dummy: shifts ncu capture window onto fused ----------------
__global__ void dummy_kernel() {}

// ================= launch 1: calcE (64 blocks, both W) | proj (192 blocks) ==========
__global__ void __launch_bounds__(256)
k1_calcE_proj(const float* __restrict__ relE, const float* __restrict__ Wr,
              const float* __restrict__ Wvv, const float* __restrict__ X,
              const float* __restrict__ Wq, const float* __restrict__ Wk,
              const float* __restrict__ Wv) {
    __shared__ float As[2][16 * 68];
    __shared__ float Bs[2][16 * 68];
    int id = blockIdx.x;
    int tid = threadIdx.x;

    if (id < 64) {
        int r = id;
        float* re = As[0];
        re[tid] = relE[r * D_ + tid];
        __syncthreads();
        int e = tid;
        float a0 = 0.f, a1 = 0.f, a2 = 0.f, a3 = 0.f;
        float c0 = 0.f, c1 = 0.f, c2 = 0.f, c3 = 0.f;
        #pragma unroll 4
        for (int d = 0; d < D_; d += 16) {
            #pragma unroll
            for (int u = 0; u < 16; u += 4) {
                float r0 = re[d+u+0], r1 = re[d+u+1], r2 = re[d+u+2], r3 = re[d+u+3];
                a0 = fmaf(r0, Wr [(size_t)(d+u+0) * D_ + e], a0);
                a1 = fmaf(r1, Wr [(size_t)(d+u+1) * D_ + e], a1);
                a2 = fmaf(r2, Wr [(size_t)(d+u+2) * D_ + e], a2);
                a3 = fmaf(r3, Wr [(size_t)(d+u+3) * D_ + e], a3);
                c0 = fmaf(r0, Wvv[(size_t)(d+u+0) * D_ + e], c0);
                c1 = fmaf(r1, Wvv[(size_t)(d+u+1) * D_ + e], c1);
                c2 = fmaf(r2, Wvv[(size_t)(d+u+2) * D_ + e], c2);
                c3 = fmaf(r3, Wvv[(size_t)(d+u+3) * D_ + e], c3);
            }
        }
        float accR = (a0 + a1) + (a2 + a3);
        float accV = (c0 + c1) + (c2 + c3);
        g_ER[r * D_ + e] = accR;
        g_EV[r * D_ + e] = accV;
        {
            int h = e >> 5, d = e & 31;
            g_EVt[((size_t)h * R_ + r) * 32 + d] = accV;
        }
        return;
    }

    // ---- proj (64x64 tiles, ping-pong double buffered) ----
    int pid = id - 64;
    int w = pid >> 6;
    const float* W = (w == 0) ? Wq : (w == 1) ? Wk : Wv;
    float* O = (w == 0) ? g_Xq : (w == 1) ? g_Xk : g_Xv;
    int rem = pid & 63;
    int n0 = (rem & 3) * 64, m0 = (rem >> 2) * 64;
    int tx = tid & 15, ty = tid >> 4;
    u64 acc2[2][4] = {};
    const float4* X4 = (const float4*)X;
    const float4* W4 = (const float4*)W;

    int am = tid >> 2, akq = tid & 3;
    int bk = tid >> 4, bnq = tid & 15;

    float4 va = X4[(size_t)(m0 + am) * 64 + akq];
    float4 vb = W4[(size_t)bk * 64 + (n0 >> 2) + bnq];
    {
        As[0][(4*akq+0)*68 + am] = va.x; As[0][(4*akq+1)*68 + am] = va.y;
        As[0][(4*akq+2)*68 + am] = va.z; As[0][(4*akq+3)*68 + am] = va.w;
        *(float4*)(&Bs[0][bk * 68 + bnq * 4]) = vb;
    }
    __syncthreads();

    for (int it = 0; it < 16; it++) {
        int cur = it & 1;
        if (it < 15) {
            va = X4[(size_t)(m0 + am) * 64 + (it + 1) * 4 + akq];
            vb = W4[(size_t)((it + 1) * 16 + bk) * 64 + (n0 >> 2) + bnq];
        }
        #pragma unroll
        for (int k = 0; k < 16; k++) {
            ulonglong2 a2 = *(const ulonglong2*)(&As[cur][k * 68 + ty * 4]);
            float4 b = *(const float4*)(&Bs[cur][k * 68 + tx * 4]);
            u64 bb0 = pack2(b.x, b.x), bb1 = pack2(b.y, b.y);
            u64 bb2 = pack2(b.z, b.z), bb3 = pack2(b.w, b.w);
            fma2(acc2[0][0], a2.x, bb0); fma2(acc2[1][0], a2.y, bb0);
            fma2(acc2[0][1], a2.x, bb1); fma2(acc2[1][1], a2.y, bb1);
            fma2(acc2[0][2], a2.x, bb2); fma2(acc2[1][2], a2.y, bb2);
            fma2(acc2[0][3], a2.x, bb3); fma2(acc2[1][3], a2.y, bb3);
        }
        if (it < 15) {
            int nxt = 1 - cur;
            As[nxt][(4*akq+0)*68 + am] = va.x; As[nxt][(4*akq+1)*68 + am] = va.y;
            As[nxt][(4*akq+2)*68 + am] = va.z; As[nxt][(4*akq+3)*68 + am] = va.w;
            *(float4*)(&Bs[nxt][bk * 68 + bnq * 4]) = vb;
        }
        __syncthreads();
    }
    #pragma unroll
    for (int mp = 0; mp < 2; mp++)
        #pragma unroll
        for (int ww = 0; ww < 4; ww++) {
            float2 f = unpack2(acc2[mp][ww]);
            int e = n0 + tx * 4 + ww, h = e >> 5, d = e & 31;
            int m = m0 + ty * 4 + mp * 2;
            int b = m >> 8, i = m & 255;
            O[(((b * H_ + h) * N_) + i) * DK_ + d] = f.x;
            m++; b = m >> 8; i = m & 255;
            O[(((b * H_ + h) * N_) + i) * DK_ + d] = f.y;
        }
}

// ================= launch 2: s0 (128 blocks) | pq (128 blocks) =================
__global__ void __launch_bounds__(256)
k2_pq_s0() {
    extern __shared__ float dynsm[];
    int id = blockIdx.x;
    int tid = threadIdx.x;

    if (id < 128) {
        float* A  = dynsm;
        float* Bs = dynsm + 32 * 132;
        int bh = id >> 2;
        int i0 = ((id >> 1) & 1) * 128, j0 = (id & 1) * 128;
        const float4* Xq4 = (const float4*)(g_Xq + (size_t)bh * N_ * DK_);
        const float4* Xk4 = (const float4*)(g_Xk + (size_t)bh * N_ * DK_);
        #pragma unroll
        for (int p = 0; p < 4; p++) {
            int l = tid + p * 256;
            int row = l >> 3, kq = l & 7;
            float4 va = Xq4[(i0 + row) * 8 + kq];
            A[(4*kq+0)*132 + row] = va.x; A[(4*kq+1)*132 + row] = va.y;
            A[(4*kq+2)*132 + row] = va.z; A[(4*kq+3)*132 + row] = va.w;
            float4 vb = Xk4[(j0 + row) * 8 + kq];
            Bs[(4*kq+0)*132 + row] = vb.x; Bs[(4*kq+1)*132 + row] = vb.y;
            Bs[(4*kq+2)*132 + row] = vb.z; Bs[(4*kq+3)*132 + row] = vb.w;
        }
        __syncthreads();
        int tx = tid & 15, ty = tid >> 4;
        u64 acc2[4][8] = {};
        #pragma unroll
        for (int k = 0; k < 32; k++) {
            ulonglong2 aa0 = *(const ulonglong2*)(A + k * 132 + ty * 8);
            ulonglong2 aa1 = *(const ulonglong2*)(A + k * 132 + ty * 8 + 4);
            float4 b0 = *(const float4*)(Bs + k * 132 + tx * 4);
            float4 b1 = *(const float4*)(Bs + k * 132 + 64 + tx * 4);
            u64 bb[8] = {pack2(b0.x,b0.x), pack2(b0.y,b0.y), pack2(b0.z,b0.z), pack2(b0.w,b0.w),
                         pack2(b1.x,b1.x), pack2(b1.y,b1.y), pack2(b1.z,b1.z), pack2(b1.w,b1.w)};
            #pragma unroll
            for (int w = 0; w < 8; w++) {
                fma2(acc2[0][w], aa0.x, bb[w]);
                fma2(acc2[1][w], aa0.y, bb[w]);
                fma2(acc2[2][w], aa1.x, bb[w]);
                fma2(acc2[3][w], aa1.y, bb[w]);
            }
        }
        float* out = g_S0 + (size_t)bh * N_ * N_;
        #pragma unroll
        for (int up = 0; up < 4; up++) {
            float4 lo0, lo1, hi0, hi1;
            float2 t;
            t = unpack2(acc2[up][0]); lo0.x = t.x; hi0.x = t.y;
            t = unpack2(acc2[up][1]); lo0.y = t.x; hi0.y = t.y;
            t = unpack2(acc2[up][2]); lo0.z = t.x; hi0.z = t.y;
            t = unpack2(acc2[up][3]); lo0.w = t.x; hi0.w = t.y;
            t = unpack2(acc2[up][4]); lo1.x = t.x; hi1.x = t.y;
            t = unpack2(acc2[up][5]); lo1.y = t.x; hi1.y = t.y;
            t = unpack2(acc2[up][6]); lo1.z = t.x; hi1.z = t.y;
            t = unpack2(acc2[up][7]); lo1.w = t.x; hi1.w = t.y;
            int gi = i0 + ty * 8 + up * 2;
            *(float4*)(out + (size_t)gi * N_ + j0 + tx * 4) = lo0;
            *(float4*)(out + (size_t)gi * N_ + j0 + 64 + tx * 4) = lo1;
            *(float4*)(out + (size_t)(gi+1) * N_ + j0 + tx * 4) = hi0;
            *(float4*)(out + (size_t)(gi+1) * N_ + j0 + 64 + tx * 4) = hi1;
        }
        return;
    }

    int pid = id - 128;
    int h = pid & 7, b = (pid >> 3) & 3, i0 = (pid >> 5) * 64;
    float* xq = dynsm;
    float* er = dynsm + 64 * 36;
    float* st = dynsm + 64 * 36 + 64 * 32;
    const float4* Xq4 = (const float4*)(g_Xq + ((size_t)(b * H_ + h) * N_ + i0) * DK_);
    #pragma unroll
    for (int p = 0; p < 2; p++) {
        int l = tid + p * 256;
        int ii = l >> 3, dq = l & 7;
        float4 v = Xq4[ii * 8 + dq];
        *(float4*)(xq + ii * 36 + dq * 4) = v;
    }
    #pragma unroll
    for (int p = 0; p < 2; p++) {
        int l = tid + p * 256;
        int r = l >> 3, dq = l & 7;
        float4 v = *(const float4*)(g_ER + (size_t)r * D_ + h * 32 + dq * 4);
        *(float4*)(er + r * 32 + dq * 4) = v;
    }
    __syncthreads();
    int ii = tid & 63, rg = tid >> 6;
    #pragma unroll
    for (int rr = 0; rr < 16; rr++) {
        int r = rg * 16 + rr;
        float acc = 0.f;
        #pragma unroll
        for (int dc = 0; dc < 8; dc++) {
            float4 xv = *(const float4*)(xq + ii * 36 + dc * 4);
            float4 ev = *(const float4*)(er + r * 32 + dc * 4);
            acc = fmaf(xv.x, ev.x, acc); acc = fmaf(xv.y, ev.y, acc);
            acc = fmaf(xv.z, ev.z, acc); acc = fmaf(xv.w, ev.w, acc);
        }
        st[ii * 65 + r] = acc;
    }
    __syncthreads();
    float* dst = g_Pq + ((size_t)(b * N_ + i0)) * 512 + h * 64;
    #pragma unroll
    for (int p = 0; p < 16; p++) {
        int idx = tid + p * 256;
        int iw = idx >> 6, r = idx & 63;
        dst[(size_t)iw * 512 + r] = st[iw * 65 + r];
    }
}

// ---------------- fused: bias + softmax + alpha + W + Z2 ----------------
#define LPAD 68
#define SM_PQ  17408
#define SM_AS  17920
#define SM_AT  21504
#define SM_WSH 24576
#define SM_TOT 25088

__global__ void __launch_bounds__(256, 2)
fused_attn_kernel(const float* __restrict__ link, const int* __restrict__ mask,
                  float* __restrict__ alpha_out) {
    extern __shared__ float sm[];
    float* L   = sm;
    float* pqS = sm + SM_PQ;
    float* aS  = sm + SM_AS;
    float* wp  = sm + SM_PQ;
    float* aT  = sm + SM_AT;
    float* wsh = sm + SM_WSH;

    int bi = blockIdx.x;
    int b = bi >> 8, i = bi & 255;
    int tid = threadIdx.x;
    int h = tid >> 5, lane = tid & 31;

    const float4* src = (const float4*)(link + (size_t)bi * (N_ * R_));
    #pragma unroll
    for (int p = 0; p < 16; p++) {
        int l = tid + p * 256;
        float4 v = src[l];
        *(float4*)(L + (l >> 4) * LPAD + ((l & 15) << 2)) = v;
    }
    pqS[tid]       = g_Pq[(size_t)bi * 512 + tid];
    pqS[tid + 256] = g_Pq[(size_t)bi * 512 + 256 + tid];

    const float* s0p = g_S0 + ((size_t)(b * H_ + h) * N_ + i) * N_;
    float s0r[8]; int mr[8];
    #pragma unroll
    for (int k = 0; k < 8; k++) {
        s0r[k] = s0p[lane + 32 * k];
        mr[k]  = mask[(size_t)bi * N_ + lane + 32 * k];
    }
    __syncthreads();

    {
        u64 acc2[H_] = {};
        const ulonglong2* Lr2 = (const ulonglong2*)(L + tid * LPAD);
        #pragma unroll
        for (int rc4 = 0; rc4 < 16; rc4++) {
            ulonglong2 lv = Lr2[rc4];
            #pragma unroll
            for (int hh = 0; hh < H_; hh++) {
                ulonglong2 pv = *(const ulonglong2*)(pqS + hh * 64 + rc4 * 4);
                fma2(acc2[hh], lv.x, pv.x);
                fma2(acc2[hh], lv.y, pv.y);
            }
        }
        #pragma unroll
        for (int hh = 0; hh < H_; hh++) {
            float2 f = unpack2(acc2[hh]);
            aS[hh * N_ + tid] = f.x + f.y;
        }
    }
    __syncthreads();

    {
        const float inv = 0.17677669529663687f;
        float v[8];
        float mx = -3.4e38f;
        #pragma unroll
        for (int k = 0; k < 8; k++) {
            int j = lane + 32 * k;
            float lg = (s0r[k] + aS[h * N_ + j]) * inv;
            if (mr[k] == 0) lg = -1e9f;
            v[k] = lg;
            mx = fmaxf(mx, lg);
        }
        #pragma unroll
        for (int o = 16; o > 0; o >>= 1) mx = fmaxf(mx, __shfl_xor_sync(0xffffffffu, mx, o));
        float s = 0.f;
        #pragma unroll
        for (int k = 0; k < 8; k++) { v[k] = __expf(v[k] - mx); s += v[k]; }
        #pragma unroll
        for (int o = 16; o > 0; o >>= 1) s += __shfl_xor_sync(0xffffffffu, s, o);
        float rs = 1.0f / s;
        float* aout = alpha_out + ((size_t)(b * H_ + h) * N_ + i) * N_;
        #pragma unroll
        for (int k = 0; k < 8; k++) {
            int j = lane + 32 * k;
            float a = v[k] * rs;
            aout[j] = a;
            aT[j * 12 + h] = a;
        }
    }
    __syncthreads();

    {
        int jc = tid >> 5, rp = tid & 31;
        const float* Lp = L + (jc * 32) * LPAD + rp * 2;
        u64 acc2[2][4] = {};
        #pragma unroll 4
        for (int u = 0; u < 32; u++) {
            float2 lv = *(const float2*)(Lp + u * LPAD);
            u64 lx = pack2(lv.x, lv.x);
            u64 ly = pack2(lv.y, lv.y);
            const ulonglong2* ap = (const ulonglong2*)(aT + (jc * 32 + u) * 12);
            ulonglong2 a01 = ap[0];
            ulonglong2 a45 = ap[1];
            fma2(acc2[0][0], lx, a01.x); fma2(acc2[0][1], lx, a01.y);
            fma2(acc2[0][2], lx, a45.x); fma2(acc2[0][3], lx, a45.y);
            fma2(acc2[1][0], ly, a01.x); fma2(acc2[1][1], ly, a01.y);
            fma2(acc2[1][2], ly, a45.x); fma2(acc2[1][3], ly, a45.y);
        }
        #pragma unroll
        for (int rr = 0; rr < 2; rr++)
            #pragma unroll
            for (int hp = 0; hp < 4; hp++) {
                float2 f = unpack2(acc2[rr][hp]);
                int r = rp * 2 + rr;
                wp[jc * 512 + (hp * 2 + 0) * 64 + r] = f.x;
                wp[jc * 512 + (hp * 2 + 1) * 64 + r] = f.y;
            }
    }
    __syncthreads();
    #pragma unroll
    for (int p = 0; p < 2; p++) {
        int idx = tid + p * 256;
        float s = 0.f;
        #pragma unroll
        for (int jc = 0; jc < 8; jc++) s += wp[jc * 512 + idx];
        wsh[idx] = s;
    }
    __syncthreads();

    {
        int d = lane;
        float acc = 0.f;
        const float* wr = wsh + h * 64;
        const float* ev = g_EVt + (size_t)h * R_ * 32 + d;
        #pragma unroll 8
        for (int r = 0; r < R_; r++) acc = fmaf(wr[r], ev[(size_t)r * 32], acc);
        g_Z2[((size_t)(b * H_ + h) * N_ + i) * DV_ + d] = acc;
    }
}

// ---------------- z: Z = alpha @ Xv + Z2 (split-j: 512 threads) -----------------
#define ZAP2 36
__global__ void __launch_bounds__(512)
z_kernel(const float* __restrict__ alpha) {
    __shared__ __align__(16) float V[256 * 32];
    __shared__ __align__(16) float A[2][2][64 * ZAP2];
    __shared__ __align__(16) float P[256 * 8];
    int bh = blockIdx.y;
    int b = bh >> 3, h = bh & 7;
    int i0 = blockIdx.x * 64;
    int tid = threadIdx.x;
    int hf = tid >> 8;
    int t  = tid & 255;

    const float4* al4 = (const float4*)(alpha + ((size_t)bh * N_ + i0) * N_);
    const float4* Xv4 = (const float4*)(g_Xv + (size_t)bh * N_ * DV_);

    #pragma unroll
    for (int p = 0; p < 4; p++) {
        int l = tid + p * 512;
        *(float4*)(V + l * 4) = Xv4[l];
    }
    int lrow0 = t >> 3, lq0 = t & 7;
    int lrow1 = (t + 256) >> 3, lq1 = t & 7;
    float4 pre0 = al4[(size_t)lrow0 * 64 + hf * 32 + lq0];
    float4 pre1 = al4[(size_t)lrow1 * 64 + hf * 32 + lq1];
    *(float4*)(&A[hf][0][lrow0 * ZAP2 + lq0 * 4]) = pre0;
    *(float4*)(&A[hf][0][lrow1 * ZAP2 + lq1 * 4]) = pre1;
    __syncthreads();

    int iy = t >> 3, dq = t & 7;
    u64 acc[2][2] = {};

    for (int c = 0; c < 4; c++) {
        int cur = c & 1;
        if (c < 3) {
            pre0 = al4[(size_t)lrow0 * 64 + hf * 32 + (c + 1) * 8 + lq0];
            pre1 = al4[(size_t)lrow1 * 64 + hf * 32 + (c + 1) * 8 + lq1];
        }
        const float* Ar0 = &A[hf][cur][(iy * 2 + 0) * ZAP2];
        const float* Ar1 = &A[hf][cur][(iy * 2 + 1) * ZAP2];
        int jbase = hf * 128 + c * 32;
        #pragma unroll 4
        for (int jt = 0; jt < 32; jt += 4) {
            float4 a0 = *(const float4*)(Ar0 + jt);
            float4 a1 = *(const float4*)(Ar1 + jt);
            int jg = (jbase + jt) * 32 + dq * 4;
            ulonglong2 v0 = *(const ulonglong2*)(V + jg);
            ulonglong2 v1 = *(const ulonglong2*)(V + jg + 32);
            ulonglong2 v2 = *(const ulonglong2*)(V + jg + 64);
            ulonglong2 v3 = *(const ulonglong2*)(V + jg + 96);
            u64 a00 = pack2(a0.x, a0.x), a10 = pack2(a1.x, a1.x);
            fma2(acc[0][0], a00, v0.x); fma2(acc[0][1], a00, v0.y);
            fma2(acc[1][0], a10, v0.x); fma2(acc[1][1], a10, v0.y);
            u64 a01 = pack2(a0.y, a0.y), a11 = pack2(a1.y, a1.y);
            fma2(acc[0][0], a01, v1.x); fma2(acc[0][1], a01, v1.y);
            fma2(acc[1][0], a11, v1.x); fma2(acc[1][1], a11, v1.y);
            u64 a02 = pack2(a0.z, a0.z), a12 = pack2(a1.z, a1.z);
            fma2(acc[0][0], a02, v2.x); fma2(acc[0][1], a02, v2.y);
            fma2(acc[1][0], a12, v2.x); fma2(acc[1][1], a12, v2.y);
            u64 a03 = pack2(a0.w, a0.w), a13 = pack2(a1.w, a1.w);
            fma2(acc[0][0], a03, v3.x); fma2(acc[0][1], a03, v3.y);
            fma2(acc[1][0], a13, v3.x); fma2(acc[1][1], a13, v3.y);
        }
        if (c < 3) {
            int nxt = 1 - cur;
            *(float4*)(&A[hf][nxt][lrow0 * ZAP2 + lq0 * 4]) = pre0;
            *(float4*)(&A[hf][nxt][lrow1 * ZAP2 + lq1 * 4]) = pre1;
        }
        __syncthreads();
    }

    float4* P4 = (float4*)P;
    if (hf == 1) {
        #pragma unroll
        for (int u = 0; u < 2; u++) {
            float2 f0 = unpack2(acc[u][0]);
            float2 f1 = unpack2(acc[u][1]);
            float4 pv = {f0.x, f0.y, f1.x, f1.y};
            P4[t * 2 + u] = pv;
        }
    }
    __syncthreads();
    if (hf == 0) {
        #pragma unroll
        for (int u = 0; u < 2; u++) {
            int i = i0 + iy * 2 + u;
            float4 z2 = *(const float4*)(g_Z2 + ((size_t)bh * N_ + i) * DV_ + dq * 4);
            float4 pv = P4[t * 2 + u];
            float2 f0 = unpack2(acc[u][0]);
            float2 f1 = unpack2(acc[u][1]);
            float4 o = {f0.x + pv.x + z2.x, f0.y + pv.y + z2.y,
                        f1.x + pv.z + z2.z, f1.y + pv.w + z2.w};
            *(float4*)(g_Zc + ((size_t)(b * N_ + i)) * D_ + h * DV_ + dq * 4) = o;
        }
    }
}

// ---------------- out_ln: T = Zc @ Wo, +residual, LayerNorm (4 rows/block) -----
__global__ void __launch_bounds__(256)
out_ln_kernel(const float* __restrict__ Wo, const float* __restrict__ qin,
              const float* __restrict__ gamma, const float* __restrict__ beta,
              float* __restrict__ out) {
    __shared__ float Bs[2][16 * 260];
    __shared__ float As[2][16 * 4];
    __shared__ float S [4 * 260];
    int m0 = blockIdx.x * 4;
    int tid = threadIdx.x;
    u64 acc2[2] = {};
    const float4* Z4 = (const float4*)g_Zc;
    const float4* W4 = (const float4*)Wo;

    int am = tid >> 2, akq = tid & 3;
    float4 va;
    float4 vb[4];

    if (tid < 16) va = Z4[(size_t)(m0 + am) * 64 + akq];
    #pragma unroll
    for (int p = 0; p < 4; p++) {
        int l = tid + p * 256;
        vb[p] = W4[(size_t)(l >> 6) * 64 + (l & 63)];
    }
    if (tid < 16) {
        As[0][(4*akq+0)*4 + am] = va.x; As[0][(4*akq+1)*4 + am] = va.y;
        As[0][(4*akq+2)*4 + am] = va.z; As[0][(4*akq+3)*4 + am] = va.w;
    }
    #pragma unroll
    for (int p = 0; p < 4; p++) {
        int l = tid + p * 256;
        *(float4*)(&Bs[0][(l >> 6) * 260 + (l & 63) * 4]) = vb[p];
    }
    __syncthreads();

    for (int it = 0; it < 16; it++) {
        int cur = it & 1;
        if (it < 15) {
            if (tid < 16) va = Z4[(size_t)(m0 + am) * 64 + (it + 1) * 4 + akq];
            #pragma unroll
            for (int p = 0; p < 4; p++) {
                int l = tid + p * 256;
                vb[p] = W4[(size_t)((it + 1) * 16 + (l >> 6)) * 64 + (l & 63)];
            }
        }
        #pragma unroll
        for (int k = 0; k < 16; k++) {
            float bn = Bs[cur][k * 260 + tid];
            u64 bb = pack2(bn, bn);
            fma2(acc2[0], *(const u64*)(&As[cur][k * 4 + 0]), bb);
            fma2(acc2[1], *(const u64*)(&As[cur][k * 4 + 2]), bb);
        }
        if (it < 15) {
            int nxt = 1 - cur;
            if (tid < 16) {
                As[nxt][(4*akq+0)*4 + am] = va.x; As[nxt][(4*akq+1)*4 + am] = va.y;
                As[nxt][(4*akq+2)*4 + am] = va.z; As[nxt][(4*akq+3)*4 + am] = va.w;
            }
            #pragma unroll
            for (int p = 0; p < 4; p++) {
                int l = tid + p * 256;
                *(float4*)(&Bs[nxt][(l >> 6) * 260 + (l & 63) * 4]) = vb[p];
            }
        }
        __syncthreads();
    }

    #pragma unroll
    for (int mp = 0; mp < 2; mp++) {
        float2 f = unpack2(acc2[mp]);
        S[(mp * 2 + 0) * 260 + tid] = f.x + qin[(size_t)(m0 + mp * 2 + 0) * D_ + tid];
        S[(mp * 2 + 1) * 260 + tid] = f.y + qin[(size_t)(m0 + mp * 2 + 1) * D_ + tid];
    }
    __syncthreads();
    {
        int w = tid >> 5, lane = tid & 31;
        if (w < 4) {
            const float* row = S + w * 260;
            float v[8];
            float s = 0.f, q2 = 0.f;
            #pragma unroll
            for (int k = 0; k < 8; k++) {
                v[k] = row[lane + 32 * k];
                s += v[k];
                q2 = fmaf(v[k], v[k], q2);
            }
            #pragma unroll
            for (int o = 16; o > 0; o >>= 1) {
                s  += __shfl_xor_sync(0xffffffffu, s, o);
                q2 += __shfl_xor_sync(0xffffffffu, q2, o);
            }
            float mu = s * (1.0f / 256.0f);
            float var = q2 * (1.0f / 256.0f) - mu * mu;
            float rstd = rsqrtf(var + EPS_);
            float* op = out + (size_t)(m0 + w) * D_;
            #pragma unroll
            for (int k = 0; k < 8; k++) {
                int n = lane + 32 * k;
                op[n] = (v[k] - mu) * rstd * gamma[n] + beta[n];
            }
        }
    }
}

// ---------------- launch (single stream, 6 launches incl. dummy) ----------------
extern "C" void kernel_launch(void* const* d_in, const int* in_sizes, int n_in,
                              void* d_out, int out_size) {
    const float* q    = (const float*)d_in[0];
    const int*   mask = (const int*)  d_in[3];
    const float* link = (const float*)d_in[4];
    const float* Wq   = (const float*)d_in[5];
    const float* Wk   = (const float*)d_in[6];
    const float* Wr   = (const float*)d_in[7];
    const float* Wv   = (const float*)d_in[8];
    const float* Wvv  = (const float*)d_in[9];
    const float* relE = (const float*)d_in[10];
    const float* Wo   = (const float*)d_in[11];
    const float* gamma= (const float*)d_in[12];
    const float* beta = (const float*)d_in[13];

    float* out_ptr   = (float*)d_out;
    float* alpha_ptr = (float*)d_out + (size_t)B_ * N_ * D_;

    static bool init = false;
    if (!init) {
        init = true;
        cudaFuncSetAttribute(fused_attn_kernel,
                             cudaFuncAttributeMaxDynamicSharedMemorySize,
                             SM_TOT * (int)sizeof(float));
    }

    dummy_kernel<<<1, 32>>>();   // shifts ncu capture slot onto fused_attn_kernel
    k1_calcE_proj<<<256, 256>>>(relE, Wr, Wvv, q, Wq, Wk, Wv);
    k2_pq_s0<<<256, 256, 8512 * sizeof(float)>>>();
    fused_attn_kernel<<<BN_, 256, SM_TOT * sizeof(float)>>>(link, mask, alpha_ptr);
    z_kernel<<<dim3(4, 32), 512>>>(alpha_ptr);
    out_ln_kernel<<<BN_ / 4, 256>>>(Wo, q, gamma, beta, out_ptr);
}

// round 16
// speedup vs baseline: 1.0493x; 1.0493x over previous
#include <cuda_runtime.h>
#include <cuda_bf16.h>
#include <cuda_fp16.h>
#include <cstdint>
#include <cstddef>

#define B_ 4
#define N_ 256
#define D_ 256
#define H_ 8
#define DK_ 32
#define DV_ 32
#define R_ 64
#define BN_ (B_*N_)
#define EPS_ 1e-6f

typedef unsigned long long u64;

// ---------------- device scratch ----------------
__device__ float g_ER[R_ * D_];
__device__ float g_EV[R_ * D_];
__device__ float g_EVt[H_ * R_ * 32];            // [h][r][d] transposed EV
__device__ float g_Xq[B_ * H_ * N_ * DK_];
__device__ float g_Xk[B_ * H_ * N_ * DK_];
__device__ float g_Xv[B_ * H_ * N_ * DV_];
__device__ float g_Pq[B_ * N_ * H_ * R_];        // [b,i,h*64+r]
__device__ float g_S0[B_ * H_ * N_ * N_];
__device__ float g_Z2[B_ * H_ * N_ * DV_];
__device__ float g_Zc[BN_ * D_];

// ---------------- f32x2 helpers ----------------
__device__ __forceinline__ void fma2(u64& d, u64 a, u64 b) {
    asm("fma.rn.f32x2 %0, %1, %2, %3;" : "=l"(d) : "l"(a), "l"(b), "l"(d));
}
__device__ __forceinline__ u64 pack2(float x, float y) {
    u64 r; asm("mov.b64 %0, {%1, %2};" : "=l"(r) : "f"(x), "f"(y)); return r;
}
__device__ __forceinline__ float2 unpack2(u64 v) {
    float2 r; asm("mov.b64 {%0, %1}, %2;" : "=f"(r.x), "=f"(r.y) : "l"(v)); return r;
}

// ---------------- dummy: shifts ncu capture window onto fused ----------------
__global__ void dummy_kernel() {}

// ================= launch 1: calcE (64 blocks, both W) | proj (192 blocks) ==========
__global__ void __launch_bounds__(256)
k1_calcE_proj(const float* __restrict__ relE, const float* __restrict__ Wr,
              const float* __restrict__ Wvv, const float* __restrict__ X,
              const float* __restrict__ Wq, const float* __restrict__ Wk,
              const float* __restrict__ Wv) {
    __shared__ float As[2][16 * 68];
    __shared__ float Bs[2][16 * 68];
    int id = blockIdx.x;
    int tid = threadIdx.x;

    if (id < 64) {
        int r = id;
        float* re = As[0];
        re[tid] = relE[r * D_ + tid];
        __syncthreads();
        int e = tid;
        float a0 = 0.f, a1 = 0.f, a2 = 0.f, a3 = 0.f;
        float c0 = 0.f, c1 = 0.f, c2 = 0.f, c3 = 0.f;
        #pragma unroll 4
        for (int d = 0; d < D_; d += 16) {
            #pragma unroll
            for (int u = 0; u < 16; u += 4) {
                float r0 = re[d+u+0], r1 = re[d+u+1], r2 = re[d+u+2], r3 = re[d+u+3];
                a0 = fmaf(r0, Wr [(size_t)(d+u+0) * D_ + e], a0);
                a1 = fmaf(r1, Wr [(size_t)(d+u+1) * D_ + e], a1);
                a2 = fmaf(r2, Wr [(size_t)(d+u+2) * D_ + e], a2);
                a3 = fmaf(r3, Wr [(size_t)(d+u+3) * D_ + e], a3);
                c0 = fmaf(r0, Wvv[(size_t)(d+u+0) * D_ + e], c0);
                c1 = fmaf(r1, Wvv[(size_t)(d+u+1) * D_ + e], c1);
                c2 = fmaf(r2, Wvv[(size_t)(d+u+2) * D_ + e], c2);
                c3 = fmaf(r3, Wvv[(size_t)(d+u+3) * D_ + e], c3);
            }
        }
        float accR = (a0 + a1) + (a2 + a3);
        float accV = (c0 + c1) + (c2 + c3);
        g_ER[r * D_ + e] = accR;
        g_EV[r * D_ + e] = accV;
        {
            int h = e >> 5, d = e & 31;
            g_EVt[((size_t)h * R_ + r) * 32 + d] = accV;
        }
        return;
    }

    // ---- proj (64x64 tiles, ping-pong double buffered) ----
    int pid = id - 64;
    int w = pid >> 6;
    const float* W = (w == 0) ? Wq : (w == 1) ? Wk : Wv;
    float* O = (w == 0) ? g_Xq : (w == 1) ? g_Xk : g_Xv;
    int rem = pid & 63;
    int n0 = (rem & 3) * 64, m0 = (rem >> 2) * 64;
    int tx = tid & 15, ty = tid >> 4;
    u64 acc2[2][4] = {};
    const float4* X4 = (const float4*)X;
    const float4* W4 = (const float4*)W;

    int am = tid >> 2, akq = tid & 3;
    int bk = tid >> 4, bnq = tid & 15;

    float4 va = X4[(size_t)(m0 + am) * 64 + akq];
    float4 vb = W4[(size_t)bk * 64 + (n0 >> 2) + bnq];
    {
        As[0][(4*akq+0)*68 + am] = va.x; As[0][(4*akq+1)*68 + am] = va.y;
        As[0][(4*akq+2)*68 + am] = va.z; As[0][(4*akq+3)*68 + am] = va.w;
        *(float4*)(&Bs[0][bk * 68 + bnq * 4]) = vb;
    }
    __syncthreads();

    for (int it = 0; it < 16; it++) {
        int cur = it & 1;
        if (it < 15) {
            va = X4[(size_t)(m0 + am) * 64 + (it + 1) * 4 + akq];
            vb = W4[(size_t)((it + 1) * 16 + bk) * 64 + (n0 >> 2) + bnq];
        }
        #pragma unroll
        for (int k = 0; k < 16; k++) {
            ulonglong2 a2 = *(const ulonglong2*)(&As[cur][k * 68 + ty * 4]);
            float4 b = *(const float4*)(&Bs[cur][k * 68 + tx * 4]);
            u64 bb0 = pack2(b.x, b.x), bb1 = pack2(b.y, b.y);
            u64 bb2 = pack2(b.z, b.z), bb3 = pack2(b.w, b.w);
            fma2(acc2[0][0], a2.x, bb0); fma2(acc2[1][0], a2.y, bb0);
            fma2(acc2[0][1], a2.x, bb1); fma2(acc2[1][1], a2.y, bb1);
            fma2(acc2[0][2], a2.x, bb2); fma2(acc2[1][2], a2.y, bb2);
            fma2(acc2[0][3], a2.x, bb3); fma2(acc2[1][3], a2.y, bb3);
        }
        if (it < 15) {
            int nxt = 1 - cur;
            As[nxt][(4*akq+0)*68 + am] = va.x; As[nxt][(4*akq+1)*68 + am] = va.y;
            As[nxt][(4*akq+2)*68 + am] = va.z; As[nxt][(4*akq+3)*68 + am] = va.w;
            *(float4*)(&Bs[nxt][bk * 68 + bnq * 4]) = vb;
        }
        __syncthreads();
    }
    #pragma unroll
    for (int mp = 0; mp < 2; mp++)
        #pragma unroll
        for (int ww = 0; ww < 4; ww++) {
            float2 f = unpack2(acc2[mp][ww]);
            int e = n0 + tx * 4 + ww, h = e >> 5, d = e & 31;
            int m = m0 + ty * 4 + mp * 2;
            int b = m >> 8, i = m & 255;
            O[(((b * H_ + h) * N_) + i) * DK_ + d] = f.x;
            m++; b = m >> 8; i = m & 255;
            O[(((b * H_ + h) * N_) + i) * DK_ + d] = f.y;
        }
}

// ================= launch 2: s0 (128 blocks) | pq (128 blocks) =================
__global__ void __launch_bounds__(256)
k2_pq_s0() {
    extern __shared__ float dynsm[];
    int id = blockIdx.x;
    int tid = threadIdx.x;

    if (id < 128) {
        float* A  = dynsm;
        float* Bs = dynsm + 32 * 132;
        int bh = id >> 2;
        int i0 = ((id >> 1) & 1) * 128, j0 = (id & 1) * 128;
        const float4* Xq4 = (const float4*)(g_Xq + (size_t)bh * N_ * DK_);
        const float4* Xk4 = (const float4*)(g_Xk + (size_t)bh * N_ * DK_);
        #pragma unroll
        for (int p = 0; p < 4; p++) {
            int l = tid + p * 256;
            int row = l >> 3, kq = l & 7;
            float4 va = Xq4[(i0 + row) * 8 + kq];
            A[(4*kq+0)*132 + row] = va.x; A[(4*kq+1)*132 + row] = va.y;
            A[(4*kq+2)*132 + row] = va.z; A[(4*kq+3)*132 + row] = va.w;
            float4 vb = Xk4[(j0 + row) * 8 + kq];
            Bs[(4*kq+0)*132 + row] = vb.x; Bs[(4*kq+1)*132 + row] = vb.y;
            Bs[(4*kq+2)*132 + row] = vb.z; Bs[(4*kq+3)*132 + row] = vb.w;
        }
        __syncthreads();
        int tx = tid & 15, ty = tid >> 4;
        u64 acc2[4][8] = {};
        #pragma unroll
        for (int k = 0; k < 32; k++) {
            ulonglong2 aa0 = *(const ulonglong2*)(A + k * 132 + ty * 8);
            ulonglong2 aa1 = *(const ulonglong2*)(A + k * 132 + ty * 8 + 4);
            float4 b0 = *(const float4*)(Bs + k * 132 + tx * 4);
            float4 b1 = *(const float4*)(Bs + k * 132 + 64 + tx * 4);
            u64 bb[8] = {pack2(b0.x,b0.x), pack2(b0.y,b0.y), pack2(b0.z,b0.z), pack2(b0.w,b0.w),
                         pack2(b1.x,b1.x), pack2(b1.y,b1.y), pack2(b1.z,b1.z), pack2(b1.w,b1.w)};
            #pragma unroll
            for (int w = 0; w < 8; w++) {
                fma2(acc2[0][w], aa0.x, bb[w]);
                fma2(acc2[1][w], aa0.y, bb[w]);
                fma2(acc2[2][w], aa1.x, bb[w]);
                fma2(acc2[3][w], aa1.y, bb[w]);
            }
        }
        float* out = g_S0 + (size_t)bh * N_ * N_;
        #pragma unroll
        for (int up = 0; up < 4; up++) {
            float4 lo0, lo1, hi0, hi1;
            float2 t;
            t = unpack2(acc2[up][0]); lo0.x = t.x; hi0.x = t.y;
            t = unpack2(acc2[up][1]); lo0.y = t.x; hi0.y = t.y;
            t = unpack2(acc2[up][2]); lo0.z = t.x; hi0.z = t.y;
            t = unpack2(acc2[up][3]); lo0.w = t.x; hi0.w = t.y;
            t = unpack2(acc2[up][4]); lo1.x = t.x; hi1.x = t.y;
            t = unpack2(acc2[up][5]); lo1.y = t.x; hi1.y = t.y;
            t = unpack2(acc2[up][6]); lo1.z = t.x; hi1.z = t.y;
            t = unpack2(acc2[up][7]); lo1.w = t.x; hi1.w = t.y;
            int gi = i0 + ty * 8 + up * 2;
            *(float4*)(out + (size_t)gi * N_ + j0 + tx * 4) = lo0;
            *(float4*)(out + (size_t)gi * N_ + j0 + 64 + tx * 4) = lo1;
            *(float4*)(out + (size_t)(gi+1) * N_ + j0 + tx * 4) = hi0;
            *(float4*)(out + (size_t)(gi+1) * N_ + j0 + 64 + tx * 4) = hi1;
        }
        return;
    }

    int pid = id - 128;
    int h = pid & 7, b = (pid >> 3) & 3, i0 = (pid >> 5) * 64;
    float* xq = dynsm;
    float* er = dynsm + 64 * 36;
    float* st = dynsm + 64 * 36 + 64 * 32;
    const float4* Xq4 = (const float4*)(g_Xq + ((size_t)(b * H_ + h) * N_ + i0) * DK_);
    #pragma unroll
    for (int p = 0; p < 2; p++) {
        int l = tid + p * 256;
        int ii = l >> 3, dq = l & 7;
        float4 v = Xq4[ii * 8 + dq];
        *(float4*)(xq + ii * 36 + dq * 4) = v;
    }
    #pragma unroll
    for (int p = 0; p < 2; p++) {
        int l = tid + p * 256;
        int r = l >> 3, dq = l & 7;
        float4 v = *(const float4*)(g_ER + (size_t)r * D_ + h * 32 + dq * 4);
        *(float4*)(er + r * 32 + dq * 4) = v;
    }
    __syncthreads();
    int ii = tid & 63, rg = tid >> 6;
    #pragma unroll
    for (int rr = 0; rr < 16; rr++) {
        int r = rg * 16 + rr;
        float acc = 0.f;
        #pragma unroll
        for (int dc = 0; dc < 8; dc++) {
            float4 xv = *(const float4*)(xq + ii * 36 + dc * 4);
            float4 ev = *(const float4*)(er + r * 32 + dc * 4);
            acc = fmaf(xv.x, ev.x, acc); acc = fmaf(xv.y, ev.y, acc);
            acc = fmaf(xv.z, ev.z, acc); acc = fmaf(xv.w, ev.w, acc);
        }
        st[ii * 65 + r] = acc;
    }
    __syncthreads();
    float* dst = g_Pq + ((size_t)(b * N_ + i0)) * 512 + h * 64;
    #pragma unroll
    for (int p = 0; p < 16; p++) {
        int idx = tid + p * 256;
        int iw = idx >> 6, r = idx & 63;
        dst[(size_t)iw * 512 + r] = st[iw * 65 + r];
    }
}

// ---------------- fused: bias + softmax + alpha + W + Z2 (half link tile) -------
// smem floats: Lh (half[256*72] = 9216 f) | overlay region 4096 f (pq 512 + aS 2048 / wp 4096)
//              | aT 3072 f | wsh 512 f   => 16896 floats = 66KB -> 3 blocks/SM
#define PADH 72
#define SMF_OVL  9216
#define SMF_PQ   9216
#define SMF_AS   9728
#define SMF_AT   13312
#define SMF_WSH  16384
#define SMF_TOT  16896

__global__ void __launch_bounds__(256, 3)
fused_attn_kernel(const float* __restrict__ link, const int* __restrict__ mask,
                  float* __restrict__ alpha_out) {
    extern __shared__ float sm[];
    __half* Lh  = (__half*)sm;
    float* pqS  = sm + SMF_PQ;
    float* aS   = sm + SMF_AS;
    float* wp   = sm + SMF_OVL;    // overlays pq+aS in phase D
    float* aT   = sm + SMF_AT;
    float* wsh  = sm + SMF_WSH;

    int bi = blockIdx.x;
    int b = bi >> 8, i = bi & 255;
    int tid = threadIdx.x;
    int h = tid >> 5, lane = tid & 31;

    // A: load link tile -> half smem (coalesced LDG128, STS64)
    const float4* src = (const float4*)(link + (size_t)bi * (N_ * R_));
    #pragma unroll
    for (int p = 0; p < 16; p++) {
        int l = tid + p * 256;
        float4 v = src[l];
        int j = l >> 4, rq = l & 15;
        __half2 h0 = __floats2half2_rn(v.x, v.y);
        __half2 h1 = __floats2half2_rn(v.z, v.w);
        uint2 pkt;
        pkt.x = *(unsigned*)&h0;
        pkt.y = *(unsigned*)&h1;
        *(uint2*)(Lh + (size_t)j * PADH + rq * 4) = pkt;
    }
    pqS[tid]       = g_Pq[(size_t)bi * 512 + tid];
    pqS[tid + 256] = g_Pq[(size_t)bi * 512 + 256 + tid];

    const float* s0p = g_S0 + ((size_t)(b * H_ + h) * N_ + i) * N_;
    float s0r[8]; int mr[8];
    #pragma unroll
    for (int k = 0; k < 8; k++) {
        s0r[k] = s0p[lane + 32 * k];
        mr[k]  = mask[(size_t)bi * N_ + lane + 32 * k];
    }
    __syncthreads();

    // B: bias[h][j] — L row (half) cvt to f32, fma2 against pq
    {
        u64 acc2[H_] = {};
        const uint4* Lr4 = (const uint4*)(Lh + (size_t)tid * PADH);
        #pragma unroll
        for (int g = 0; g < 8; g++) {
            uint4 lw = Lr4[g];
            float2 f0 = __half22float2(*(__half2*)&lw.x);
            float2 f1 = __half22float2(*(__half2*)&lw.y);
            float2 f2 = __half22float2(*(__half2*)&lw.z);
            float2 f3 = __half22float2(*(__half2*)&lw.w);
            u64 l0 = pack2(f0.x, f0.y), l1 = pack2(f1.x, f1.y);
            u64 l2 = pack2(f2.x, f2.y), l3 = pack2(f3.x, f3.y);
            #pragma unroll
            for (int hh = 0; hh < H_; hh++) {
                const ulonglong2* pv = (const ulonglong2*)(pqS + hh * 64 + g * 8);
                ulonglong2 p01 = pv[0];
                ulonglong2 p23 = pv[1];
                fma2(acc2[hh], l0, p01.x);
                fma2(acc2[hh], l1, p01.y);
                fma2(acc2[hh], l2, p23.x);
                fma2(acc2[hh], l3, p23.y);
            }
        }
        #pragma unroll
        for (int hh = 0; hh < H_; hh++) {
            float2 f = unpack2(acc2[hh]);
            aS[hh * N_ + tid] = f.x + f.y;
        }
    }
    __syncthreads();

    // C: softmax (warp per head)
    {
        const float inv = 0.17677669529663687f;
        float v[8];
        float mx = -3.4e38f;
        #pragma unroll
        for (int k = 0; k < 8; k++) {
            int j = lane + 32 * k;
            float lg = (s0r[k] + aS[h * N_ + j]) * inv;
            if (mr[k] == 0) lg = -1e9f;
            v[k] = lg;
            mx = fmaxf(mx, lg);
        }
        #pragma unroll
        for (int o = 16; o > 0; o >>= 1) mx = fmaxf(mx, __shfl_xor_sync(0xffffffffu, mx, o));
        float s = 0.f;
        #pragma unroll
        for (int k = 0; k < 8; k++) { v[k] = __expf(v[k] - mx); s += v[k]; }
        #pragma unroll
        for (int o = 16; o > 0; o >>= 1) s += __shfl_xor_sync(0xffffffffu, s, o);
        float rs = 1.0f / s;
        float* aout = alpha_out + ((size_t)(b * H_ + h) * N_ + i) * N_;
        #pragma unroll
        for (int k = 0; k < 8; k++) {
            int j = lane + 32 * k;
            float a = v[k] * rs;
            aout[j] = a;
            aT[j * 12 + h] = a;
        }
    }
    __syncthreads();

    // D: W[h][r] partials — half L, f32 accumulate
    {
        int jc = tid >> 5, rp = tid & 31;
        const __half2* Lp = (const __half2*)(Lh + (size_t)(jc * 32) * PADH) + rp;
        u64 acc2[2][4] = {};
        #pragma unroll 4
        for (int u = 0; u < 32; u++) {
            __half2 lh = Lp[u * (PADH / 2)];
            float2 lf = __half22float2(lh);
            u64 lx = pack2(lf.x, lf.x);
            u64 ly = pack2(lf.y, lf.y);
            const ulonglong2* ap = (const ulonglong2*)(aT + (jc * 32 + u) * 12);
            ulonglong2 a01 = ap[0];
            ulonglong2 a45 = ap[1];
            fma2(acc2[0][0], lx, a01.x); fma2(acc2[0][1], lx, a01.y);
            fma2(acc2[0][2], lx, a45.x); fma2(acc2[0][3], lx, a45.y);
            fma2(acc2[1][0], ly, a01.x); fma2(acc2[1][1], ly, a01.y);
            fma2(acc2[1][2], ly, a45.x); fma2(acc2[1][3], ly, a45.y);
        }
        #pragma unroll
        for (int rr = 0; rr < 2; rr++)
            #pragma unroll
            for (int hp = 0; hp < 4; hp++) {
                float2 f = unpack2(acc2[rr][hp]);
                int r = rp * 2 + rr;
                wp[jc * 512 + (hp * 2 + 0) * 64 + r] = f.x;
                wp[jc * 512 + (hp * 2 + 1) * 64 + r] = f.y;
            }
    }
    __syncthreads();
    #pragma unroll
    for (int p = 0; p < 2; p++) {
        int idx = tid + p * 256;
        float s = 0.f;
        #pragma unroll
        for (int jc = 0; jc < 8; jc++) s += wp[jc * 512 + idx];
        wsh[idx] = s;
    }
    __syncthreads();

    // E: Z2
    {
        int d = lane;
        float acc = 0.f;
        const float* wr = wsh + h * 64;
        const float* ev = g_EVt + (size_t)h * R_ * 32 + d;
        #pragma unroll 8
        for (int r = 0; r < R_; r++) acc = fmaf(wr[r], ev[(size_t)r * 32], acc);
        g_Z2[((size_t)(b * H_ + h) * N_ + i) * DV_ + d] = acc;
    }
}

// ---------------- z: Z = alpha @ Xv + Z2 (split-j: 512 threads) -----------------
#define ZAP2 36
__global__ void __launch_bounds__(512)
z_kernel(const float* __restrict__ alpha) {
    __shared__ __align__(16) float V[256 * 32];
    __shared__ __align__(16) float A[2][2][64 * ZAP2];
    __shared__ __align__(16) float P[256 * 8];
    int bh = blockIdx.y;
    int b = bh >> 3, h = bh & 7;
    int i0 = blockIdx.x * 64;
    int tid = threadIdx.x;
    int hf = tid >> 8;
    int t  = tid & 255;

    const float4* al4 = (const float4*)(alpha + ((size_t)bh * N_ + i0) * N_);
    const float4* Xv4 = (const float4*)(g_Xv + (size_t)bh * N_ * DV_);

    #pragma unroll
    for (int p = 0; p < 4; p++) {
        int l = tid + p * 512;
        *(float4*)(V + l * 4) = Xv4[l];
    }
    int lrow0 = t >> 3, lq0 = t & 7;
    int lrow1 = (t + 256) >> 3, lq1 = t & 7;
    float4 pre0 = al4[(size_t)lrow0 * 64 + hf * 32 + lq0];
    float4 pre1 = al4[(size_t)lrow1 * 64 + hf * 32 + lq1];
    *(float4*)(&A[hf][0][lrow0 * ZAP2 + lq0 * 4]) = pre0;
    *(float4*)(&A[hf][0][lrow1 * ZAP2 + lq1 * 4]) = pre1;
    __syncthreads();

    int iy = t >> 3, dq = t & 7;
    u64 acc[2][2] = {};

    for (int c = 0; c < 4; c++) {
        int cur = c & 1;
        if (c < 3) {
            pre0 = al4[(size_t)lrow0 * 64 + hf * 32 + (c + 1) * 8 + lq0];
            pre1 = al4[(size_t)lrow1 * 64 + hf * 32 + (c + 1) * 8 + lq1];
        }
        const float* Ar0 = &A[hf][cur][(iy * 2 + 0) * ZAP2];
        const float* Ar1 = &A[hf][cur][(iy * 2 + 1) * ZAP2];
        int jbase = hf * 128 + c * 32;
        #pragma unroll 4
        for (int jt = 0; jt < 32; jt += 4) {
            float4 a0 = *(const float4*)(Ar0 + jt);
            float4 a1 = *(const float4*)(Ar1 + jt);
            int jg = (jbase + jt) * 32 + dq * 4;
            ulonglong2 v0 = *(const ulonglong2*)(V + jg);
            ulonglong2 v1 = *(const ulonglong2*)(V + jg + 32);
            ulonglong2 v2 = *(const ulonglong2*)(V + jg + 64);
            ulonglong2 v3 = *(const ulonglong2*)(V + jg + 96);
            u64 a00 = pack2(a0.x, a0.x), a10 = pack2(a1.x, a1.x);
            fma2(acc[0][0], a00, v0.x); fma2(acc[0][1], a00, v0.y);
            fma2(acc[1][0], a10, v0.x); fma2(acc[1][1], a10, v0.y);
            u64 a01 = pack2(a0.y, a0.y), a11 = pack2(a1.y, a1.y);
            fma2(acc[0][0], a01, v1.x); fma2(acc[0][1], a01, v1.y);
            fma2(acc[1][0], a11, v1.x); fma2(acc[1][1], a11, v1.y);
            u64 a02 = pack2(a0.z, a0.z), a12 = pack2(a1.z, a1.z);
            fma2(acc[0][0], a02, v2.x); fma2(acc[0][1], a02, v2.y);
            fma2(acc[1][0], a12, v2.x); fma2(acc[1][1], a12, v2.y);
            u64 a03 = pack2(a0.w, a0.w), a13 = pack2(a1.w, a1.w);
            fma2(acc[0][0], a03, v3.x); fma2(acc[0][1], a03, v3.y);
            fma2(acc[1][0], a13, v3.x); fma2(acc[1][1], a13, v3.y);
        }
        if (c < 3) {
            int nxt = 1 - cur;
            *(float4*)(&A[hf][nxt][lrow0 * ZAP2 + lq0 * 4]) = pre0;
            *(float4*)(&A[hf][nxt][lrow1 * ZAP2 + lq1 * 4]) = pre1;
        }
        __syncthreads();
    }

    float4* P4 = (float4*)P;
    if (hf == 1) {
        #pragma unroll
        for (int u = 0; u < 2; u++) {
            float2 f0 = unpack2(acc[u][0]);
            float2 f1 = unpack2(acc[u][1]);
            float4 pv = {f0.x, f0.y, f1.x, f1.y};
            P4[t * 2 + u] = pv;
        }
    }
    __syncthreads();
    if (hf == 0) {
        #pragma unroll
        for (int u = 0; u < 2; u++) {
            int i = i0 + iy * 2 + u;
            float4 z2 = *(const float4*)(g_Z2 + ((size_t)bh * N_ + i) * DV_ + dq * 4);
            float4 pv = P4[t * 2 + u];
            float2 f0 = unpack2(acc[u][0]);
            float2 f1 = unpack2(acc[u][1]);
            float4 o = {f0.x + pv.x + z2.x, f0.y + pv.y + z2.y,
                        f1.x + pv.z + z2.z, f1.y + pv.w + z2.w};
            *(float4*)(g_Zc + ((size_t)(b * N_ + i)) * D_ + h * DV_ + dq * 4) = o;
        }
    }
}

// ---------------- out_ln: T = Zc @ Wo, +residual, LayerNorm (4 rows/block) -----
__global__ void __launch_bounds__(256)
out_ln_kernel(const float* __restrict__ Wo, const float* __restrict__ qin,
              const float* __restrict__ gamma, const float* __restrict__ beta,
              float* __restrict__ out) {
    __shared__ float Bs[2][16 * 260];
    __shared__ float As[2][16 * 4];
    __shared__ float S [4 * 260];
    int m0 = blockIdx.x * 4;
    int tid = threadIdx.x;
    u64 acc2[2] = {};
    const float4* Z4 = (const float4*)g_Zc;
    const float4* W4 = (const float4*)Wo;

    int am = tid >> 2, akq = tid & 3;
    float4 va;
    float4 vb[4];

    if (tid < 16) va = Z4[(size_t)(m0 + am) * 64 + akq];
    #pragma unroll
    for (int p = 0; p < 4; p++) {
        int l = tid + p * 256;
        vb[p] = W4[(size_t)(l >> 6) * 64 + (l & 63)];
    }
    if (tid < 16) {
        As[0][(4*akq+0)*4 + am] = va.x; As[0][(4*akq+1)*4 + am] = va.y;
        As[0][(4*akq+2)*4 + am] = va.z; As[0][(4*akq+3)*4 + am] = va.w;
    }
    #pragma unroll
    for (int p = 0; p < 4; p++) {
        int l = tid + p * 256;
        *(float4*)(&Bs[0][(l >> 6) * 260 + (l & 63) * 4]) = vb[p];
    }
    __syncthreads();

    for (int it = 0; it < 16; it++) {
        int cur = it & 1;
        if (it < 15) {
            if (tid < 16) va = Z4[(size_t)(m0 + am) * 64 + (it + 1) * 4 + akq];
            #pragma unroll
            for (int p = 0; p < 4; p++) {
                int l = tid + p * 256;
                vb[p] = W4[(size_t)((it + 1) * 16 + (l >> 6)) * 64 + (l & 63)];
            }
        }
        #pragma unroll
        for (int k = 0; k < 16; k++) {
            float bn = Bs[cur][k * 260 + tid];
            u64 bb = pack2(bn, bn);
            fma2(acc2[0], *(const u64*)(&As[cur][k * 4 + 0]), bb);
            fma2(acc2[1], *(const u64*)(&As[cur][k * 4 + 2]), bb);
        }
        if (it < 15) {
            int nxt = 1 - cur;
            if (tid < 16) {
                As[nxt][(4*akq+0)*4 + am] = va.x; As[nxt][(4*akq+1)*4 + am] = va.y;
                As[nxt][(4*akq+2)*4 + am] = va.z; As[nxt][(4*akq+3)*4 + am] = va.w;
            }
            #pragma unroll
            for (int p = 0; p < 4; p++) {
                int l = tid + p * 256;
                *(float4*)(&Bs[nxt][(l >> 6) * 260 + (l & 63) * 4]) = vb[p];
            }
        }
        __syncthreads();
    }

    #pragma unroll
    for (int mp = 0; mp < 2; mp++) {
        float2 f = unpack2(acc2[mp]);
        S[(mp * 2 + 0) * 260 + tid] = f.x + qin[(size_t)(m0 + mp * 2 + 0) * D_ + tid];
        S[(mp * 2 + 1) * 260 + tid] = f.y + qin[(size_t)(m0 + mp * 2 + 1) * D_ + tid];
    }
    __syncthreads();
    {
        int w = tid >> 5, lane = tid & 31;
        if (w < 4) {
            const float* row = S + w * 260;
            float v[8];
            float s = 0.f, q2 = 0.f;
            #pragma unroll
            for (int k = 0; k < 8; k++) {
                v[k] = row[lane + 32 * k];
                s += v[k];
                q2 = fmaf(v[k], v[k], q2);
            }
            #pragma unroll
            for (int o = 16; o > 0; o >>= 1) {
                s  += __shfl_xor_sync(0xffffffffu, s, o);
                q2 += __shfl_xor_sync(0xffffffffu, q2, o);
            }
            float mu = s * (1.0f / 256.0f);
            float var = q2 * (1.0f / 256.0f) - mu * mu;
            float rstd = rsqrtf(var + EPS_);
            float* op = out + (size_t)(m0 + w) * D_;
            #pragma unroll
            for (int k = 0; k < 8; k++) {
                int n = lane + 32 * k;
                op[n] = (v[k] - mu) * rstd * gamma[n] + beta[n];
            }
        }
    }
}

// ---------------- launch (single stream, 6 launches incl. dummy) ----------------
extern "C" void kernel_launch(void* const* d_in, const int* in_sizes, int n_in,
                              void* d_out, int out_size) {
    const float* q    = (const float*)d_in[0];
    const int*   mask = (const int*)  d_in[3];
    const float* link = (const float*)d_in[4];
    const float* Wq   = (const float*)d_in[5];
    const float* Wk   = (const float*)d_in[6];
    const float* Wr   = (const float*)d_in[7];
    const float* Wv   = (const float*)d_in[8];
    const float* Wvv  = (const float*)d_in[9];
    const float* relE = (const float*)d_in[10];
    const float* Wo   = (const float*)d_in[11];
    const float* gamma= (const float*)d_in[12];
    const float* beta = (const float*)d_in[13];

    float* out_ptr   = (float*)d_out;
    float* alpha_ptr = (float*)d_out + (size_t)B_ * N_ * D_;

    static bool init = false;
    if (!init) {
        init = true;
        cudaFuncSetAttribute(fused_attn_kernel,
                             cudaFuncAttributeMaxDynamicSharedMemorySize,
                             SMF_TOT * (int)sizeof(float));
    }

    dummy_kernel<<<1, 32>>>();   // keeps ncu capture slot on fused_attn_kernel
    k1_calcE_proj<<<256, 256>>>(relE, Wr, Wvv, q, Wq, Wk, Wv);
    k2_pq_s0<<<256, 256, 8512 * sizeof(float)>>>();
    fused_attn_kernel<<<BN_, 256, SMF_TOT * sizeof(float)>>>(link, mask, alpha_ptr);
    z_kernel<<<dim3(4, 32), 512>>>(alpha_ptr);
    out_ln_kernel<<<BN_ / 4, 256>>>(Wo, q, gamma, beta, out_ptr);
}